// round 11
// baseline (speedup 1.0000x reference)
#include <cuda_runtime.h>
#include <cstdint>

// FirstFFTLinearLayer: 64-point forward complex DFT along dim 1 of
// [B=16, N=64, H=256, W=256] f32 (separate real/imag inputs).
// Output: REAL PART only, f32, [B, N, H, W]. (Established R1-R9.)
//
// R9 (121.3us): full in-register FFT, 151 regs -> 12 warps/SM, DRAM 81.7%.
// R10 lesson: do NOT interleave compute into the load stream.
// This round: split-half FFT to cut register pressure ->
//   stage-64 butterfly at load time; half A (64 f32) stays in registers,
//   half B (64 f32) parked in thread-private smem (tid-indexed, no syncs,
//   conflict-free); FFT-32 on A -> even-k stores; reload B -> FFT-32 ->
//   odd-k stores. Peak regs ~100 -> 5 CTAs/SM (20 warps) vs 3 (12).

#define HW 65536          // H*W
#define NFFT 64
#define BATCH 16
#define NPIX (BATCH * HW) // 1,048,576
#define TPB 128

__global__ __launch_bounds__(TPB)
void fft64_kernel(const float* __restrict__ re,
                  const float* __restrict__ im,
                  float* __restrict__ out) {
    __shared__ float2 tw[NFFT];
    __shared__ float  sB[64 * TPB];   // half B: 32 complex per thread, tid-strided
    {
        int t = threadIdx.x;
        if (t < NFFT) {
            float s, c;
            // exp(-2*pi*i*t/64) = cos(pi t/32) - i sin(pi t/32)
            sincospif(-(float)t * (1.0f / 32.0f), &s, &c);
            tw[t] = make_float2(c, s);
        }
    }
    __syncthreads();  // tw only; sB is thread-private, never needs a barrier

    const int tid = threadIdx.x;
    int idx = blockIdx.x * TPB + tid;
    int s_  = idx & (HW - 1);
    int b   = idx >> 16;
    const size_t base = (size_t)b * (NFFT * (size_t)HW) + (size_t)s_;
    const float* pr  = re + base;
    const float* pim = im + base;

    float ar[32], ai[32];   // half A (sums) — lives in registers

    // Phase 1: 4 waves of 32 independent loads (keeps MLP high per wave),
    // stage-64 butterfly per j; twiddled diffs -> thread-private smem.
#pragma unroll
    for (int wv = 0; wv < 4; wv++) {
        float ur[8], vr[8], ui[8], vi[8];
#pragma unroll
        for (int t = 0; t < 8; t++) {           // 32 batched loads
            int j = wv * 8 + t;
            ur[t] = pr [(size_t)j * HW];
            vr[t] = pr [(size_t)(j + 32) * HW];
            ui[t] = pim[(size_t)j * HW];
            vi[t] = pim[(size_t)(j + 32) * HW];
        }
#pragma unroll
        for (int t = 0; t < 8; t++) {
            int j = wv * 8 + t;
            ar[j] = ur[t] + vr[t];
            ai[j] = ui[t] + vi[t];
            float dr = ur[t] - vr[t], di = ui[t] - vi[t];
            float2 w = tw[j];
            sB[(2 * j    ) * TPB + tid] = dr * w.x - di * w.y;  // B real
            sB[(2 * j + 1) * TPB + tid] = dr * w.y + di * w.x;  // B imag
        }
    }

    // FFT-32 over a 32-complex register array: stages m=32..2 of the
    // original 64-pt DIF restricted to one half (twiddle step = 64/m).
#define FFT32_STAGES(xr, xi)                                              \
    _Pragma("unroll")                                                     \
    for (int m = 32; m >= 2; m >>= 1) {                                   \
        const int half = m >> 1;                                          \
        const int step = NFFT / m;                                        \
        _Pragma("unroll")                                                 \
        for (int k = 0; k < 32; k += m) {                                 \
            _Pragma("unroll")                                             \
            for (int j = 0; j < half; j++) {                              \
                float u_r = xr[k + j],        u_i = xi[k + j];            \
                float v_r = xr[k + j + half], v_i = xi[k + j + half];     \
                xr[k + j] = u_r + v_r;                                    \
                xi[k + j] = u_i + v_i;                                    \
                float d_r = u_r - v_r, d_i = u_i - v_i;                   \
                float2 w = tw[(j * step) & (NFFT - 1)];                   \
                xr[k + j + half] = d_r * w.x - d_i * w.y;                 \
                xi[k + j + half] = d_r * w.y + d_i * w.x;                 \
            }                                                             \
        }                                                                 \
    }

    float* o = out + base;

    // Half A -> even output bins: out[2r] = A_slot[brev5(r)], real part.
    FFT32_STAGES(ar, ai)
#pragma unroll
    for (int r = 0; r < 32; r++) {
        int p = (int)(__brev((unsigned)r) >> 27);  // 5-bit bit-reverse
        o[(size_t)(2 * r) * HW] = ar[p];
    }

    // Half B: reload from smem (ar/ai registers now dead), FFT-32,
    // odd output bins: out[2r+1] = B_slot[brev5(r)], real part.
    float br[32], bi[32];
#pragma unroll
    for (int j = 0; j < 32; j++) {
        br[j] = sB[(2 * j    ) * TPB + tid];
        bi[j] = sB[(2 * j + 1) * TPB + tid];
    }
    FFT32_STAGES(br, bi)
#pragma unroll
    for (int r = 0; r < 32; r++) {
        int p = (int)(__brev((unsigned)r) >> 27);
        o[(size_t)(2 * r + 1) * HW] = br[p];
    }
#undef FFT32_STAGES
}

extern "C" void kernel_launch(void* const* d_in, const int* in_sizes, int n_in,
                              void* d_out, int out_size) {
    // Weight = smallest input (unused); remaining two in d_in order = (re, im).
    int wmin = 0;
    for (int i = 1; i < n_in; i++)
        if (in_sizes[i] < in_sizes[wmin]) wmin = i;

    const float* adc_real = nullptr;
    const float* adc_imag = nullptr;
    for (int i = 0; i < n_in; i++) {
        if (i == wmin) continue;
        if (!adc_real)      adc_real = (const float*)d_in[i];
        else if (!adc_imag) adc_imag = (const float*)d_in[i];
    }
    if (!adc_real || !adc_imag) return;

    float* out = (float*)d_out;
    const int blocks = NPIX / TPB;  // 8192
    fft64_kernel<<<blocks, TPB>>>(adc_real, adc_imag, out);
}